// round 2
// baseline (speedup 1.0000x reference)
#include <cuda_runtime.h>
#include <cstdint>

// Problem dims
#define NTOK 4096      // n = 8*512
#define HID  512       // h (both j and k dims)
#define ROLES 64       // R
#define NCOLS (HID*ROLES) // 32768 columns of U_flat

// Tiling
#define MT 128         // m (token) tile
#define NT 128         // column tile (k-chunk within one role)
#define KT 32          // j tile per smem stage
#define NCHUNK (HID/NT)   // 4 column-chunks per role
#define KITER (HID/KT)    // 16 k-stages

__device__ __forceinline__ uint32_t f2tf32(float f) {
    uint32_t u;
    asm("cvt.rna.tf32.f32 %0, %1;" : "=r"(u) : "f"(f));
    return u;
}

__global__ __launch_bounds__(256, 2)
void bilinear_scorer_kernel(const float* __restrict__ pred,
                            const float* __restrict__ args,
                            const float* __restrict__ U,
                            const float* __restrict__ bias1,
                            const float* __restrict__ bias2,
                            float* __restrict__ out)
{
    // Padded for conflict-free mma-fragment LDS:
    //  A row pad 36 words -> bank = (4*row + col) % 32, rows 0..7 x cols 0..3 distinct
    //  B row pad 136 words -> bank = (8*row + col) % 32, rows 0..3 x cols 0..7 distinct
    __shared__ uint32_t sA[MT][36];
    __shared__ uint32_t sB[KT][136];
    __shared__ float    sred[MT];

    const int m_base = blockIdx.x * MT;
    const int r      = blockIdx.y;

    const int tid    = threadIdx.x;
    const int lane   = tid & 31;
    const int warp   = tid >> 5;
    const int warp_m = warp & 1;   // 2 warps along m  (64 rows each)
    const int warp_n = warp >> 1;  // 4 warps along n  (32 cols each)
    const int gid    = lane >> 2;  // 0..7
    const int tig    = lane & 3;   // 0..3

    float outp[8];                 // per-thread out partials, [wm][i]
    #pragma unroll
    for (int t = 0; t < 8; t++) outp[t] = 0.f;

    for (int nc = 0; nc < NCHUNK; nc++) {
        const int c_base = r * HID + nc * NT;   // global U_flat column base

        float acc[4][4][4];
        #pragma unroll
        for (int a = 0; a < 4; a++)
            #pragma unroll
            for (int b = 0; b < 4; b++)
                #pragma unroll
                for (int c = 0; c < 4; c++)
                    acc[a][b][c] = 0.f;

        for (int kt = 0; kt < KITER; kt++) {
            // ---- stage A tile: pred[m_base:+128, kt*32:+32], rounded to tf32 ----
            #pragma unroll
            for (int it = 0; it < 4; it++) {
                int q   = tid + it * 256;          // 0..1023 quads
                int row = q >> 3;
                int qc  = q & 7;
                const float4 v = *reinterpret_cast<const float4*>(
                    &pred[(m_base + row) * HID + kt * KT + qc * 4]);
                uint4 w;
                w.x = f2tf32(v.x); w.y = f2tf32(v.y);
                w.z = f2tf32(v.z); w.w = f2tf32(v.w);
                *reinterpret_cast<uint4*>(&sA[row][qc * 4]) = w;
            }
            // ---- stage B tile: U_flat[kt*32:+32, c_base:+128] ----
            #pragma unroll
            for (int it = 0; it < 4; it++) {
                int q   = tid + it * 256;
                int row = q >> 5;
                int qc  = q & 31;
                const float4 v = *reinterpret_cast<const float4*>(
                    &U[(size_t)(kt * KT + row) * NCOLS + c_base + qc * 4]);
                uint4 w;
                w.x = f2tf32(v.x); w.y = f2tf32(v.y);
                w.z = f2tf32(v.z); w.w = f2tf32(v.w);
                *reinterpret_cast<uint4*>(&sB[row][qc * 4]) = w;
            }
            __syncthreads();

            // ---- 4 k-steps of m16n8k8 tf32 mma ----
            #pragma unroll
            for (int ks = 0; ks < 4; ks++) {
                uint32_t af[4][4];
                #pragma unroll
                for (int wm = 0; wm < 4; wm++) {
                    int arow = warp_m * 64 + wm * 16 + gid;
                    int ac   = ks * 8 + tig;
                    af[wm][0] = sA[arow    ][ac    ];
                    af[wm][1] = sA[arow + 8][ac    ];
                    af[wm][2] = sA[arow    ][ac + 4];
                    af[wm][3] = sA[arow + 8][ac + 4];
                }
                uint32_t bf[4][2];
                #pragma unroll
                for (int wn = 0; wn < 4; wn++) {
                    int bcol = warp_n * 32 + wn * 8 + gid;
                    int brow = ks * 8 + tig;
                    bf[wn][0] = sB[brow    ][bcol];
                    bf[wn][1] = sB[brow + 4][bcol];
                }
                #pragma unroll
                for (int wm = 0; wm < 4; wm++)
                    #pragma unroll
                    for (int wn = 0; wn < 4; wn++) {
                        asm volatile(
                            "mma.sync.aligned.m16n8k8.row.col.f32.tf32.tf32.f32 "
                            "{%0,%1,%2,%3}, {%4,%5,%6,%7}, {%8,%9}, {%0,%1,%2,%3};"
                            : "+f"(acc[wm][wn][0]), "+f"(acc[wm][wn][1]),
                              "+f"(acc[wm][wn][2]), "+f"(acc[wm][wn][3])
                            : "r"(af[wm][0]), "r"(af[wm][1]),
                              "r"(af[wm][2]), "r"(af[wm][3]),
                              "r"(bf[wn][0]), "r"(bf[wn][1]));
                    }
            }
            __syncthreads();
        }

        // ---- fused epilogue for this chunk: out += (C1 + bias1) * args ----
        #pragma unroll
        for (int wm = 0; wm < 4; wm++)
            #pragma unroll
            for (int i = 0; i < 2; i++) {
                int m_loc = warp_m * 64 + wm * 16 + gid + i * 8;
                const float* arow = args + (size_t)(m_base + m_loc) * HID + nc * NT;
                float s = 0.f;
                #pragma unroll
                for (int wn = 0; wn < 4; wn++)
                    #pragma unroll
                    for (int j = 0; j < 2; j++) {
                        int c_loc = warp_n * 32 + wn * 8 + tig * 2 + j;
                        float c1 = acc[wm][wn][i * 2 + j] + __ldg(&bias1[c_base + c_loc]);
                        s += c1 * __ldg(&arow[c_loc]);
                    }
                outp[wm * 2 + i] += s;
            }
    }

    // ---- reduce partials: over tig (columns within warp) ----
    #pragma unroll
    for (int t = 0; t < 8; t++) {
        outp[t] += __shfl_xor_sync(0xffffffffu, outp[t], 1);
        outp[t] += __shfl_xor_sync(0xffffffffu, outp[t], 2);
    }

    // ---- cross n-warp reduce via shared, then single store per output ----
    if (tid < MT) sred[tid] = 0.f;
    __syncthreads();
    if (tig == 0) {
        #pragma unroll
        for (int wm = 0; wm < 4; wm++)
            #pragma unroll
            for (int i = 0; i < 2; i++) {
                int m_loc = warp_m * 64 + wm * 16 + gid + i * 8;
                atomicAdd(&sred[m_loc], outp[wm * 2 + i]);
            }
    }
    __syncthreads();
    if (tid < MT) {
        out[(size_t)(m_base + tid) * ROLES + r] = sred[tid] + __ldg(&bias2[r]);
    }
}

extern "C" void kernel_launch(void* const* d_in, const int* in_sizes, int n_in,
                              void* d_out, int out_size) {
    const float* pred  = (const float*)d_in[0];
    const float* args  = (const float*)d_in[1];
    const float* U     = (const float*)d_in[2];
    const float* bias1 = (const float*)d_in[3];
    const float* bias2 = (const float*)d_in[4];
    float* out = (float*)d_out;

    dim3 grid(NTOK / MT, ROLES);   // 32 x 64 = 2048 blocks
    bilinear_scorer_kernel<<<grid, 256>>>(pred, args, U, bias1, bias2, out);
}

// round 4
// speedup vs baseline: 1.1799x; 1.1799x over previous
#include <cuda_runtime.h>
#include <cstdint>

// ---------------- problem dims ----------------
#define NTOK 4096
#define HID  512
#define ROLES 64
#define NCOLS (HID*ROLES)      // 32768

// ---------------- tiling ----------------
#define MT 256                 // m rows per block
#define NT 128                 // cols per nc chunk (block covers full role via 4 chunks)
#define KT 32                  // K per stage
#define NCHUNK (HID/NT)        // 4
#define KITER (HID/KT)         // 16

// ---------------- smem (bytes) ----------------
#define SA_BYTES (MT*128)          // 32768  (256 rows x 32 tf32 words)
#define SB_BYTES (NT*128)          // 16384  (128 c-rows x 32 tf32 words)
#define SM_A   0
#define SM_B   (2*SA_BYTES)
#define SM_RED (SM_B + 2*SB_BYTES) // 98304
#define SM_TOTAL (SM_RED + MT*4)   // 99328

// ---------------- device scratch (static, no runtime alloc) ----------------
__device__ uint32_t g_predT[(size_t)NTOK * HID];   // pred as tf32 bits [n][j]   (8 MB)
__device__ uint32_t g_Ut[(size_t)NCOLS * HID];     // U^T as tf32 bits  [c][j]   (64 MB)

// ---------------- helpers ----------------
__device__ __forceinline__ uint32_t f2tf32(float f) {
    uint32_t u; asm("cvt.rna.tf32.f32 %0, %1;" : "=r"(u) : "f"(f)); return u;
}
__device__ __forceinline__ uint32_t s2u(const void* p) {
    uint32_t a;
    asm("{ .reg .u64 t; cvta.to.shared.u64 t, %1; cvt.u32.u64 %0, t; }" : "=r"(a) : "l"(p));
    return a;
}
__device__ __forceinline__ void cp16(uint32_t dst_smem, const uint32_t* src) {
    asm volatile("cp.async.cg.shared.global [%0], [%1], 16;"
                 :: "r"(dst_smem), "l"(__cvta_generic_to_global(src)));
}
// value at (row, col-word) of a 128B-row SW128-swizzled tile
__device__ __forceinline__ uint32_t lds_tile(const char* base, int row, int col) {
    return *reinterpret_cast<const uint32_t*>(base + row * 128 + 4 * (col ^ ((row & 7) << 2)));
}

// ---------------- pre-pass 1: pred f32 -> tf32 bits ----------------
__global__ __launch_bounds__(256)
void pred_cvt_kernel(const float* __restrict__ pred)
{
    size_t i = ((size_t)blockIdx.x * 256 + threadIdx.x) * 4;
    const float4 v = *reinterpret_cast<const float4*>(pred + i);
    uint4 w;
    w.x = f2tf32(v.x); w.y = f2tf32(v.y); w.z = f2tf32(v.z); w.w = f2tf32(v.w);
    *reinterpret_cast<uint4*>(g_predT + i) = w;
}

// ---------------- pre-pass 2: U[j][c] -> g_Ut[c][j] (tf32) ----------------
__global__ __launch_bounds__(256)
void transpose_cvt_kernel(const float* __restrict__ U)
{
    __shared__ float t[32][33];
    const int c0 = blockIdx.x * 32;
    const int j0 = blockIdx.y * 32;
    const int tx = threadIdx.x & 31, ty = threadIdx.x >> 5;
    #pragma unroll
    for (int i = 0; i < 4; i++) {
        int j = ty + i * 8;
        t[j][tx] = U[(size_t)(j0 + j) * NCOLS + c0 + tx];
    }
    __syncthreads();
    #pragma unroll
    for (int i = 0; i < 4; i++) {
        int cc = ty + i * 8;
        g_Ut[(size_t)(c0 + cc) * HID + j0 + tx] = f2tf32(t[tx][cc]);
    }
}

// ---------------- main kernel ----------------
__global__ __launch_bounds__(256, 1)
void bilinear_main(const float* __restrict__ args,
                   const float* __restrict__ bias1,
                   const float* __restrict__ bias2,
                   float* __restrict__ out)
{
    extern __shared__ char smem[];
    const uint32_t sb = s2u(smem);
    const int tid  = threadIdx.x;
    const int lane = tid & 31, wid = tid >> 5;
    const int warp_m = wid & 3;     // 4 bands of 64 rows
    const int warp_n = wid >> 2;    // 2 bands of 64 cols
    const int gid = lane >> 2, tig = lane & 3;
    const int m_base = blockIdx.x * MT;
    const int r = blockIdx.y;

    float outp[8];
    #pragma unroll
    for (int t = 0; t < 8; t++) outp[t] = 0.f;

    for (int nc = 0; nc < NCHUNK; nc++) {
        float acc[4][8][4];
        #pragma unroll
        for (int a = 0; a < 4; a++)
            #pragma unroll
            for (int b = 0; b < 8; b++)
                #pragma unroll
                for (int c = 0; c < 4; c++) acc[a][b][c] = 0.f;

        const uint32_t* srcA0 = g_predT + (size_t)m_base * HID;
        const uint32_t* srcB0 = g_Ut + (size_t)(r * HID + nc * NT) * HID;

        // ---- prologue: stage kt=0 into buf 0 ----
        {
            const uint32_t aS = sb + SM_A, bS = sb + SM_B;
            #pragma unroll
            for (int it = 0; it < 8; it++) {
                int q = tid + it * 256, row = q >> 3, qc = q & 7;
                cp16(aS + row * 128 + ((qc * 16) ^ ((row & 7) << 4)),
                     srcA0 + (size_t)row * HID + qc * 4);
            }
            #pragma unroll
            for (int it = 0; it < 4; it++) {
                int q = tid + it * 256, row = q >> 3, qc = q & 7;
                cp16(bS + row * 128 + ((qc * 16) ^ ((row & 7) << 4)),
                     srcB0 + (size_t)row * HID + qc * 4);
            }
            asm volatile("cp.async.commit_group;" ::: "memory");
        }

        for (int kt = 0; kt < KITER; kt++) {
            const int buf = kt & 1;
            if (kt + 1 < KITER) {
                // stage kt+1 into other buffer, then wait for kt's data
                const uint32_t aS = sb + SM_A + (buf ^ 1) * SA_BYTES;
                const uint32_t bS = sb + SM_B + (buf ^ 1) * SB_BYTES;
                const uint32_t* sA = srcA0 + (kt + 1) * KT;
                const uint32_t* sB = srcB0 + (kt + 1) * KT;
                #pragma unroll
                for (int it = 0; it < 8; it++) {
                    int q = tid + it * 256, row = q >> 3, qc = q & 7;
                    cp16(aS + row * 128 + ((qc * 16) ^ ((row & 7) << 4)),
                         sA + (size_t)row * HID + qc * 4);
                }
                #pragma unroll
                for (int it = 0; it < 4; it++) {
                    int q = tid + it * 256, row = q >> 3, qc = q & 7;
                    cp16(bS + row * 128 + ((qc * 16) ^ ((row & 7) << 4)),
                         sB + (size_t)row * HID + qc * 4);
                }
                asm volatile("cp.async.commit_group;" ::: "memory");
                asm volatile("cp.async.wait_group 1;" ::: "memory");
            } else {
                asm volatile("cp.async.wait_group 0;" ::: "memory");
            }
            __syncthreads();

            const char* aT = smem + SM_A + buf * SA_BYTES;
            const char* bT = smem + SM_B + buf * SB_BYTES;
            #pragma unroll
            for (int ks = 0; ks < 4; ks++) {
                uint32_t af[4][4];
                #pragma unroll
                for (int wm = 0; wm < 4; wm++) {
                    int arow = warp_m * 64 + wm * 16 + gid;
                    int ac   = ks * 8 + tig;
                    af[wm][0] = lds_tile(aT, arow,     ac);
                    af[wm][1] = lds_tile(aT, arow + 8, ac);
                    af[wm][2] = lds_tile(aT, arow,     ac + 4);
                    af[wm][3] = lds_tile(aT, arow + 8, ac + 4);
                }
                #pragma unroll
                for (int wn = 0; wn < 8; wn++) {
                    int bc   = warp_n * 64 + wn * 8 + gid;
                    int brow = ks * 8 + tig;
                    uint32_t b0 = lds_tile(bT, bc, brow);
                    uint32_t b1 = lds_tile(bT, bc, brow + 4);
                    #pragma unroll
                    for (int wm = 0; wm < 4; wm++) {
                        asm volatile(
                            "mma.sync.aligned.m16n8k8.row.col.f32.tf32.tf32.f32 "
                            "{%0,%1,%2,%3}, {%4,%5,%6,%7}, {%8,%9}, {%0,%1,%2,%3};"
                            : "+f"(acc[wm][wn][0]), "+f"(acc[wm][wn][1]),
                              "+f"(acc[wm][wn][2]), "+f"(acc[wm][wn][3])
                            : "r"(af[wm][0]), "r"(af[wm][1]),
                              "r"(af[wm][2]), "r"(af[wm][3]),
                              "r"(b0), "r"(b1));
                    }
                }
            }
            __syncthreads();
        }

        // ---- fused epilogue: outp += (C1 + bias1) . args over this chunk ----
        const float* b1 = bias1 + (size_t)r * HID + nc * NT;
        #pragma unroll
        for (int wm = 0; wm < 4; wm++)
            #pragma unroll
            for (int i = 0; i < 2; i++) {
                int m_loc = warp_m * 64 + wm * 16 + gid + i * 8;
                const float* arow = args + (size_t)(m_base + m_loc) * HID + nc * NT;
                float s = 0.f;
                #pragma unroll
                for (int wn = 0; wn < 8; wn++) {
                    int c = warp_n * 64 + wn * 8 + tig * 2;
                    const float2 av = *reinterpret_cast<const float2*>(arow + c);
                    const float2 bv = *reinterpret_cast<const float2*>(b1 + c);
                    s += (acc[wm][wn][i * 2]     + bv.x) * av.x
                       + (acc[wm][wn][i * 2 + 1] + bv.y) * av.y;
                }
                outp[wm * 2 + i] += s;
            }
    }

    // ---- reduce over tig lanes ----
    #pragma unroll
    for (int t = 0; t < 8; t++) {
        outp[t] += __shfl_xor_sync(0xffffffffu, outp[t], 1);
        outp[t] += __shfl_xor_sync(0xffffffffu, outp[t], 2);
    }

    // ---- cross warp_n reduce via shared, one store per output ----
    float* sred = reinterpret_cast<float*>(smem + SM_RED);
    sred[tid] = 0.f;
    __syncthreads();
    if (tig == 0) {
        #pragma unroll
        for (int wm = 0; wm < 4; wm++)
            #pragma unroll
            for (int i = 0; i < 2; i++)
                atomicAdd(&sred[warp_m * 64 + wm * 16 + gid + i * 8], outp[wm * 2 + i]);
    }
    __syncthreads();
    out[(size_t)(m_base + tid) * ROLES + r] = sred[tid] + __ldg(&bias2[r]);
}

// ---------------- launch ----------------
extern "C" void kernel_launch(void* const* d_in, const int* in_sizes, int n_in,
                              void* d_out, int out_size) {
    const float* pred  = (const float*)d_in[0];
    const float* args  = (const float*)d_in[1];
    const float* U     = (const float*)d_in[2];
    const float* bias1 = (const float*)d_in[3];
    const float* bias2 = (const float*)d_in[4];
    float* out = (float*)d_out;

    cudaFuncSetAttribute(bilinear_main, cudaFuncAttributeMaxDynamicSharedMemorySize, SM_TOTAL);

    pred_cvt_kernel<<<(NTOK * HID) / (256 * 4), 256>>>(pred);
    transpose_cvt_kernel<<<dim3(NCOLS / 32, HID / 32), 256>>>(U);
    bilinear_main<<<dim3(NTOK / MT, ROLES), 256, SM_TOTAL>>>(args, bias1, bias2, out);
}

// round 5
// speedup vs baseline: 1.3209x; 1.1195x over previous
#include <cuda_runtime.h>
#include <cstdint>

// ---------------- problem dims ----------------
#define NTOK 4096
#define HID  512
#define ROLES 64
#define NCOLS (HID*ROLES)      // 32768

// ---------------- tiling ----------------
#define MT 128                 // m rows per block
#define NT 128                 // cols per nc chunk
#define KT 32                  // K per stage
#define NCHUNK (HID/NT)        // 4
#define KITER (HID/KT)         // 16

// ---------------- smem (bytes) ----------------
#define SA_BYTES (MT*128)          // 16384
#define SB_BYTES (NT*128)          // 16384
#define SM_A   0
#define SM_B   (2*SA_BYTES)        // 32768
#define SM_RED (SM_B + 2*SB_BYTES) // 65536
#define SM_TOTAL (SM_RED + MT*4)   // 66048  (2 CTAs/SM = 132KB)

// ---------------- device scratch (static, no runtime alloc) ----------------
__device__ uint32_t g_predT[(size_t)NTOK * HID];   // pred as tf32 bits [n][j]   (8 MB)
__device__ uint32_t g_Ut[(size_t)NCOLS * HID];     // U^T as tf32 bits  [c][j]   (64 MB)

// ---------------- helpers ----------------
__device__ __forceinline__ uint32_t f2tf32(float f) {
    uint32_t u; asm("cvt.rna.tf32.f32 %0, %1;" : "=r"(u) : "f"(f)); return u;
}
__device__ __forceinline__ uint32_t s2u(const void* p) {
    uint32_t a;
    asm("{ .reg .u64 t; cvta.to.shared.u64 t, %1; cvt.u32.u64 %0, t; }" : "=r"(a) : "l"(p));
    return a;
}
__device__ __forceinline__ void cp16(uint32_t dst_smem, const uint32_t* src) {
    asm volatile("cp.async.cg.shared.global [%0], [%1], 16;"
                 :: "r"(dst_smem), "l"(__cvta_generic_to_global(src)));
}
// value at (row, col-word) of a 128B-row SW128-swizzled tile
__device__ __forceinline__ uint32_t lds_tile(const char* base, int row, int col) {
    return *reinterpret_cast<const uint32_t*>(base + row * 128 + 4 * (col ^ ((row & 7) << 2)));
}

// ---------------- pre-pass 1: pred f32 -> tf32 bits ----------------
__global__ __launch_bounds__(256)
void pred_cvt_kernel(const float* __restrict__ pred)
{
    size_t i = ((size_t)blockIdx.x * 256 + threadIdx.x) * 4;
    const float4 v = *reinterpret_cast<const float4*>(pred + i);
    uint4 w;
    w.x = f2tf32(v.x); w.y = f2tf32(v.y); w.z = f2tf32(v.z); w.w = f2tf32(v.w);
    *reinterpret_cast<uint4*>(g_predT + i) = w;
}

// ---------------- pre-pass 2: U[j][c] -> g_Ut[c][j] (tf32) ----------------
__global__ __launch_bounds__(256)
void transpose_cvt_kernel(const float* __restrict__ U)
{
    __shared__ float t[32][33];
    const int c0 = blockIdx.x * 32;
    const int j0 = blockIdx.y * 32;
    const int tx = threadIdx.x & 31, ty = threadIdx.x >> 5;
    #pragma unroll
    for (int i = 0; i < 4; i++) {
        int j = ty + i * 8;
        t[j][tx] = U[(size_t)(j0 + j) * NCOLS + c0 + tx];
    }
    __syncthreads();
    #pragma unroll
    for (int i = 0; i < 4; i++) {
        int cc = ty + i * 8;
        g_Ut[(size_t)(c0 + cc) * HID + j0 + tx] = f2tf32(t[tx][cc]);
    }
}

// ---------------- main kernel: 128 threads (4 warps), 2 CTAs/SM ----------------
__global__ __launch_bounds__(128, 2)
void bilinear_main(const float* __restrict__ args,
                   const float* __restrict__ bias1,
                   const float* __restrict__ bias2,
                   float* __restrict__ out)
{
    extern __shared__ char smem[];
    const uint32_t sb = s2u(smem);
    const int tid  = threadIdx.x;
    const int lane = tid & 31, wid = tid >> 5;
    const int warp_m = wid & 1;     // 2 bands of 64 rows
    const int warp_n = wid >> 1;    // 2 bands of 64 cols
    const int gid = lane >> 2, tig = lane & 3;
    const int m_base = blockIdx.x * MT;
    const int r = blockIdx.y;

    float outp[8];
    #pragma unroll
    for (int t = 0; t < 8; t++) outp[t] = 0.f;

    for (int nc = 0; nc < NCHUNK; nc++) {
        float acc[4][8][4];
        #pragma unroll
        for (int a = 0; a < 4; a++)
            #pragma unroll
            for (int b = 0; b < 8; b++)
                #pragma unroll
                for (int c = 0; c < 4; c++) acc[a][b][c] = 0.f;

        const uint32_t* srcA0 = g_predT + (size_t)m_base * HID;
        const uint32_t* srcB0 = g_Ut + (size_t)(r * HID + nc * NT) * HID;

        // ---- prologue: stage kt=0 into buf 0 ----
        {
            const uint32_t aS = sb + SM_A, bS = sb + SM_B;
            #pragma unroll
            for (int it = 0; it < 8; it++) {
                int q = tid + it * 128, row = q >> 3, qc = q & 7;
                cp16(aS + row * 128 + ((qc * 16) ^ ((row & 7) << 4)),
                     srcA0 + (size_t)row * HID + qc * 4);
            }
            #pragma unroll
            for (int it = 0; it < 8; it++) {
                int q = tid + it * 128, row = q >> 3, qc = q & 7;
                cp16(bS + row * 128 + ((qc * 16) ^ ((row & 7) << 4)),
                     srcB0 + (size_t)row * HID + qc * 4);
            }
            asm volatile("cp.async.commit_group;" ::: "memory");
        }

        for (int kt = 0; kt < KITER; kt++) {
            const int buf = kt & 1;
            if (kt + 1 < KITER) {
                const uint32_t aS = sb + SM_A + (buf ^ 1) * SA_BYTES;
                const uint32_t bS = sb + SM_B + (buf ^ 1) * SB_BYTES;
                const uint32_t* sA = srcA0 + (kt + 1) * KT;
                const uint32_t* sB = srcB0 + (kt + 1) * KT;
                #pragma unroll
                for (int it = 0; it < 8; it++) {
                    int q = tid + it * 128, row = q >> 3, qc = q & 7;
                    cp16(aS + row * 128 + ((qc * 16) ^ ((row & 7) << 4)),
                         sA + (size_t)row * HID + qc * 4);
                }
                #pragma unroll
                for (int it = 0; it < 8; it++) {
                    int q = tid + it * 128, row = q >> 3, qc = q & 7;
                    cp16(bS + row * 128 + ((qc * 16) ^ ((row & 7) << 4)),
                         sB + (size_t)row * HID + qc * 4);
                }
                asm volatile("cp.async.commit_group;" ::: "memory");
                asm volatile("cp.async.wait_group 1;" ::: "memory");
            } else {
                asm volatile("cp.async.wait_group 0;" ::: "memory");
            }
            __syncthreads();

            const char* aT = smem + SM_A + buf * SA_BYTES;
            const char* bT = smem + SM_B + buf * SB_BYTES;
            #pragma unroll
            for (int ks = 0; ks < 4; ks++) {
                uint32_t af[4][4];
                #pragma unroll
                for (int wm = 0; wm < 4; wm++) {
                    int arow = warp_m * 64 + wm * 16 + gid;
                    int ac   = ks * 8 + tig;
                    af[wm][0] = lds_tile(aT, arow,     ac);
                    af[wm][1] = lds_tile(aT, arow + 8, ac);
                    af[wm][2] = lds_tile(aT, arow,     ac + 4);
                    af[wm][3] = lds_tile(aT, arow + 8, ac + 4);
                }
                #pragma unroll
                for (int wn = 0; wn < 8; wn++) {
                    int bc   = warp_n * 64 + wn * 8 + gid;
                    int brow = ks * 8 + tig;
                    uint32_t b0 = lds_tile(bT, bc, brow);
                    uint32_t b1 = lds_tile(bT, bc, brow + 4);
                    #pragma unroll
                    for (int wm = 0; wm < 4; wm++) {
                        asm volatile(
                            "mma.sync.aligned.m16n8k8.row.col.f32.tf32.tf32.f32 "
                            "{%0,%1,%2,%3}, {%4,%5,%6,%7}, {%8,%9}, {%0,%1,%2,%3};"
                            : "+f"(acc[wm][wn][0]), "+f"(acc[wm][wn][1]),
                              "+f"(acc[wm][wn][2]), "+f"(acc[wm][wn][3])
                            : "r"(af[wm][0]), "r"(af[wm][1]),
                              "r"(af[wm][2]), "r"(af[wm][3]),
                              "r"(b0), "r"(b1));
                    }
                }
            }
            __syncthreads();
        }

        // ---- fused epilogue: outp += (C1 + bias1) . args over this chunk ----
        const float* b1 = bias1 + (size_t)r * HID + nc * NT;
        #pragma unroll
        for (int wm = 0; wm < 4; wm++)
            #pragma unroll
            for (int i = 0; i < 2; i++) {
                int m_loc = warp_m * 64 + wm * 16 + gid + i * 8;
                const float* arow = args + (size_t)(m_base + m_loc) * HID + nc * NT;
                float s = 0.f;
                #pragma unroll
                for (int wn = 0; wn < 8; wn++) {
                    int c = warp_n * 64 + wn * 8 + tig * 2;
                    const float2 av = *reinterpret_cast<const float2*>(arow + c);
                    const float2 bv = *reinterpret_cast<const float2*>(b1 + c);
                    s += (acc[wm][wn][i * 2]     + bv.x) * av.x
                       + (acc[wm][wn][i * 2 + 1] + bv.y) * av.y;
                }
                outp[wm * 2 + i] += s;
            }
    }

    // ---- reduce over tig lanes ----
    #pragma unroll
    for (int t = 0; t < 8; t++) {
        outp[t] += __shfl_xor_sync(0xffffffffu, outp[t], 1);
        outp[t] += __shfl_xor_sync(0xffffffffu, outp[t], 2);
    }

    // ---- cross warp_n reduce via shared, one store per output row ----
    float* sred = reinterpret_cast<float*>(smem + SM_RED);
    sred[tid] = 0.f;
    __syncthreads();
    if (tig == 0) {
        #pragma unroll
        for (int wm = 0; wm < 4; wm++)
            #pragma unroll
            for (int i = 0; i < 2; i++)
                atomicAdd(&sred[warp_m * 64 + wm * 16 + gid + i * 8], outp[wm * 2 + i]);
    }
    __syncthreads();
    out[(size_t)(m_base + tid) * ROLES + r] = sred[tid] + __ldg(&bias2[r]);
}

// ---------------- launch ----------------
extern "C" void kernel_launch(void* const* d_in, const int* in_sizes, int n_in,
                              void* d_out, int out_size) {
    const float* pred  = (const float*)d_in[0];
    const float* args  = (const float*)d_in[1];
    const float* U     = (const float*)d_in[2];
    const float* bias1 = (const float*)d_in[3];
    const float* bias2 = (const float*)d_in[4];
    float* out = (float*)d_out;

    cudaFuncSetAttribute(bilinear_main, cudaFuncAttributeMaxDynamicSharedMemorySize, SM_TOTAL);

    pred_cvt_kernel<<<(NTOK * HID) / (256 * 4), 256>>>(pred);
    transpose_cvt_kernel<<<dim3(NCOLS / 32, HID / 32), 256>>>(U);
    bilinear_main<<<dim3(NTOK / MT, ROLES), 128, SM_TOTAL>>>(args, bias1, bias2, out);
}

// round 8
// speedup vs baseline: 1.3420x; 1.0160x over previous
#include <cuda_runtime.h>
#include <cstdint>

// ---------------- problem dims ----------------
#define NTOK 4096
#define HID  512
#define ROLES 64
#define NCOLS (HID*ROLES)      // 32768

// ---------------- tiling ----------------
#define MT 128                 // m rows per block
#define NT 128                 // cols per nc chunk
#define KT 32                  // K per stage
#define NCHUNK (HID/NT)        // 4
#define KITER (HID/KT)         // 16
#define NSTAGE_TOT (NCHUNK*KITER)  // 64 flat stages
#define NBUF 3

// ---------------- smem (bytes) ----------------
#define SA_BYTES (MT*128)           // 16384 per stage
#define SB_BYTES (NT*128)           // 16384 per stage
#define SM_A   0
#define SM_B   (NBUF*SA_BYTES)      // 49152
#define SM_RED (SM_B + NBUF*SB_BYTES) // 98304
#define SM_TOTAL (SM_RED + MT*4)    // 98816  (2 CTAs/SM -> 193KB/SM)

// ---------------- device scratch (static, no runtime alloc) ----------------
__device__ uint32_t g_predT[(size_t)NTOK * HID];   // pred as tf32 bits [n][j]   (8 MB)
__device__ uint32_t g_Ut[(size_t)NCOLS * HID];     // U^T as tf32 bits  [c][j]   (64 MB)

// ---------------- helpers ----------------
__device__ __forceinline__ uint32_t f2tf32(float f) {
    uint32_t u; asm("cvt.rna.tf32.f32 %0, %1;" : "=r"(u) : "f"(f)); return u;
}
__device__ __forceinline__ uint32_t s2u(const void* p) {
    uint32_t a;
    asm("{ .reg .u64 t; cvta.to.shared.u64 t, %1; cvt.u32.u64 %0, t; }" : "=r"(a) : "l"(p));
    return a;
}
__device__ __forceinline__ void cp16(uint32_t dst_smem, const uint32_t* src) {
    asm volatile("cp.async.cg.shared.global [%0], [%1], 16;"
                 :: "r"(dst_smem), "l"(__cvta_generic_to_global(src)));
}
// value at (row, col-word) of a 128B-row SW128-swizzled tile
__device__ __forceinline__ uint32_t lds_tile(const char* base, int row, int col) {
    return *reinterpret_cast<const uint32_t*>(base + row * 128 + 4 * (col ^ ((row & 7) << 2)));
}

// ---------------- pre-pass 1: pred f32 -> tf32 bits ----------------
__global__ __launch_bounds__(256)
void pred_cvt_kernel(const float* __restrict__ pred)
{
    size_t i = ((size_t)blockIdx.x * 256 + threadIdx.x) * 4;
    const float4 v = *reinterpret_cast<const float4*>(pred + i);
    uint4 w;
    w.x = f2tf32(v.x); w.y = f2tf32(v.y); w.z = f2tf32(v.z); w.w = f2tf32(v.w);
    *reinterpret_cast<uint4*>(g_predT + i) = w;
}

// ---------------- pre-pass 2: U[j][c] -> g_Ut[c][j] (tf32) ----------------
__global__ __launch_bounds__(256)
void transpose_cvt_kernel(const float* __restrict__ U)
{
    __shared__ float t[32][33];
    const int c0 = blockIdx.x * 32;
    const int j0 = blockIdx.y * 32;
    const int tx = threadIdx.x & 31, ty = threadIdx.x >> 5;
    #pragma unroll
    for (int i = 0; i < 4; i++) {
        int j = ty + i * 8;
        t[j][tx] = U[(size_t)(j0 + j) * NCOLS + c0 + tx];
    }
    __syncthreads();
    #pragma unroll
    for (int i = 0; i < 4; i++) {
        int cc = ty + i * 8;
        g_Ut[(size_t)(c0 + cc) * HID + j0 + tx] = f2tf32(t[tx][cc]);
    }
}

// ---------------- main kernel: 128 threads (4 warps), 2 CTAs/SM ----------------
__global__ __launch_bounds__(128, 2)
void bilinear_main(const float* __restrict__ args,
                   const float* __restrict__ bias1,
                   const float* __restrict__ bias2,
                   float* __restrict__ out)
{
    extern __shared__ char smem[];
    const uint32_t sb = s2u(smem);
    const int tid  = threadIdx.x;
    const int lane = tid & 31, wid = tid >> 5;
    const int warp_m = wid & 1;     // 2 bands of 64 rows
    const int warp_n = wid >> 1;    // 2 bands of 64 cols
    const int gid = lane >> 2, tig = lane & 3;
    const int m_base = blockIdx.x * MT;
    const int r = blockIdx.y;

    const uint32_t* __restrict__ srcA = g_predT + (size_t)m_base * HID;
    const uint32_t* __restrict__ srcB = g_Ut + (size_t)r * HID * HID;  // role base [c_local][j]

    // per-thread staging coords (stage layout is identical every stage)
    const int sRow = tid >> 3;          // 0..15 (x8 iters -> 128 rows)
    const int sQc  = tid & 7;           // quad within row
    const uint32_t sOff = (uint32_t)sRow * 128 + (((uint32_t)sQc * 16) ^ (((uint32_t)sRow & 7) << 4));
    const size_t  sSrc = (size_t)sRow * HID + sQc * 4;

    float outp[8];
    #pragma unroll
    for (int t = 0; t < 8; t++) outp[t] = 0.f;

    float acc[4][8][4];
    #pragma unroll
    for (int a = 0; a < 4; a++)
        #pragma unroll
        for (int b = 0; b < 8; b++)
            #pragma unroll
            for (int c = 0; c < 4; c++) acc[a][b][c] = 0.f;

    // ---- stage issue: flat stage index s -> (nc = s>>4, kt = s&15), buffer = s%3 ----
    auto issue_stage = [&](int s, int buf) {
        const int kt = s & (KITER - 1);
        const int nc = s >> 4;
        const uint32_t aS = sb + SM_A + buf * SA_BYTES;
        const uint32_t bS = sb + SM_B + buf * SB_BYTES;
        const uint32_t* a0 = srcA + kt * KT + sSrc;
        const uint32_t* b0 = srcB + (size_t)(nc * NT) * HID + kt * KT + sSrc;
        #pragma unroll
        for (int it = 0; it < 8; it++)
            cp16(aS + sOff + it * 16 * 128, a0 + (size_t)it * 16 * HID);
        #pragma unroll
        for (int it = 0; it < 8; it++)
            cp16(bS + sOff + it * 16 * 128, b0 + (size_t)it * 16 * HID);
    };

    // ---- prologue: stages 0,1 into buffers 0,1 ----
    issue_stage(0, 0);
    asm volatile("cp.async.commit_group;" ::: "memory");
    issue_stage(1, 1);
    asm volatile("cp.async.commit_group;" ::: "memory");

    int buf = 0;        // s % 3
    int buf2 = 2;       // (s+2) % 3
    for (int s = 0; s < NSTAGE_TOT; s++) {
        asm volatile("cp.async.wait_group 1;" ::: "memory");
        __syncthreads();
        if (s + 2 < NSTAGE_TOT) issue_stage(s + 2, buf2);
        asm volatile("cp.async.commit_group;" ::: "memory");   // empty group in tail keeps accounting

        const char* aT = smem + SM_A + buf * SA_BYTES;
        const char* bT = smem + SM_B + buf * SB_BYTES;
        #pragma unroll
        for (int ks = 0; ks < 4; ks++) {
            uint32_t af[4][4];
            #pragma unroll
            for (int wm = 0; wm < 4; wm++) {
                int arow = warp_m * 64 + wm * 16 + gid;
                int ac   = ks * 8 + tig;
                af[wm][0] = lds_tile(aT, arow,     ac);
                af[wm][1] = lds_tile(aT, arow + 8, ac);
                af[wm][2] = lds_tile(aT, arow,     ac + 4);
                af[wm][3] = lds_tile(aT, arow + 8, ac + 4);
            }
            #pragma unroll
            for (int wn = 0; wn < 8; wn++) {
                int bc   = warp_n * 64 + wn * 8 + gid;
                int brow = ks * 8 + tig;
                uint32_t b0 = lds_tile(bT, bc, brow);
                uint32_t b1 = lds_tile(bT, bc, brow + 4);
                #pragma unroll
                for (int wm = 0; wm < 4; wm++) {
                    asm volatile(
                        "mma.sync.aligned.m16n8k8.row.col.f32.tf32.tf32.f32 "
                        "{%0,%1,%2,%3}, {%4,%5,%6,%7}, {%8,%9}, {%0,%1,%2,%3};"
                        : "+f"(acc[wm][wn][0]), "+f"(acc[wm][wn][1]),
                          "+f"(acc[wm][wn][2]), "+f"(acc[wm][wn][3])
                        : "r"(af[wm][0]), "r"(af[wm][1]),
                          "r"(af[wm][2]), "r"(af[wm][3]),
                          "r"(b0), "r"(b1));
                }
            }
        }

        // ---- chunk boundary: fused epilogue (overlaps with in-flight cp.async) ----
        if ((s & (KITER - 1)) == (KITER - 1)) {
            const int nc = s >> 4;
            const float* b1p = bias1 + (size_t)r * HID + nc * NT;
            #pragma unroll
            for (int wm = 0; wm < 4; wm++)
                #pragma unroll
                for (int i = 0; i < 2; i++) {
                    int m_loc = warp_m * 64 + wm * 16 + gid + i * 8;
                    const float* arow = args + (size_t)(m_base + m_loc) * HID + nc * NT;
                    float sm = 0.f;
                    #pragma unroll
                    for (int wn = 0; wn < 8; wn++) {
                        int c = warp_n * 64 + wn * 8 + tig * 2;
                        const float2 av = *reinterpret_cast<const float2*>(arow + c);
                        const float2 bv = *reinterpret_cast<const float2*>(b1p + c);
                        sm += (acc[wm][wn][i * 2]     + bv.x) * av.x
                            + (acc[wm][wn][i * 2 + 1] + bv.y) * av.y;
                    }
                    outp[wm * 2 + i] += sm;
                }
            #pragma unroll
            for (int a = 0; a < 4; a++)
                #pragma unroll
                for (int b = 0; b < 8; b++)
                    #pragma unroll
                    for (int c = 0; c < 4; c++) acc[a][b][c] = 0.f;
        }

        buf  = (buf  == 2) ? 0 : buf  + 1;
        buf2 = (buf2 == 2) ? 0 : buf2 + 1;
    }

    // ---- reduce over tig lanes ----
    #pragma unroll
    for (int t = 0; t < 8; t++) {
        outp[t] += __shfl_xor_sync(0xffffffffu, outp[t], 1);
        outp[t] += __shfl_xor_sync(0xffffffffu, outp[t], 2);
    }

    // ---- cross warp_n reduce via shared, one store per output row ----
    float* sred = reinterpret_cast<float*>(smem + SM_RED);
    sred[tid] = 0.f;
    __syncthreads();
    if (tig == 0) {
        #pragma unroll
        for (int wm = 0; wm < 4; wm++)
            #pragma unroll
            for (int i = 0; i < 2; i++)
                atomicAdd(&sred[warp_m * 64 + wm * 16 + gid + i * 8], outp[wm * 2 + i]);
    }
    __syncthreads();
    out[(size_t)(m_base + tid) * ROLES + r] = sred[tid] + __ldg(&bias2[r]);
}

// ---------------- launch ----------------
extern "C" void kernel_launch(void* const* d_in, const int* in_sizes, int n_in,
                              void* d_out, int out_size) {
    const float* pred  = (const float*)d_in[0];
    const float* args  = (const float*)d_in[1];
    const float* U     = (const float*)d_in[2];
    const float* bias1 = (const float*)d_in[3];
    const float* bias2 = (const float*)d_in[4];
    float* out = (float*)d_out;

    cudaFuncSetAttribute(bilinear_main, cudaFuncAttributeMaxDynamicSharedMemorySize, SM_TOTAL);

    pred_cvt_kernel<<<(NTOK * HID) / (256 * 4), 256>>>(pred);
    transpose_cvt_kernel<<<dim3(NCOLS / 32, HID / 32), 256>>>(U);
    bilinear_main<<<dim3(NTOK / MT, ROLES), 128, SM_TOTAL>>>(args, bias1, bias2, out);
}

// round 10
// speedup vs baseline: 2.6544x; 1.9779x over previous
#include <cuda_runtime.h>
#include <cuda_fp16.h>
#include <cstdint>

// ---------------- problem dims ----------------
#define NTOK 4096
#define HID  512
#define ROLES 64
#define NCOLS (HID*ROLES)      // 32768
#define HW    (HID/2)          // 256 fp16x2 words per row

// ---------------- tiling ----------------
#define MT 128                 // m rows per block
#define NT 128                 // cols per nc chunk
#define KT 64                  // K elems per stage (= 32 words = 128B row)
#define NCHUNK (HID/NT)        // 4
#define KITER (HID/KT)         // 8
#define NSTAGE_TOT (NCHUNK*KITER)  // 32 flat stages
#define NBUF 3

// ---------------- smem (bytes) ----------------
#define SA_BYTES (MT*128)           // 16384 per stage (128 rows x 128B)
#define SB_BYTES (NT*128)           // 16384 per stage
#define SM_A   0
#define SM_B   (NBUF*SA_BYTES)      // 49152
#define SM_RED (SM_B + NBUF*SB_BYTES) // 98304
#define SM_TOTAL (SM_RED + MT*4)    // 98816  (2 CTAs/SM -> 193KB/SM)

// ---------------- device scratch (static, no runtime alloc) ----------------
__device__ uint32_t g_predH[(size_t)NTOK * HW];    // pred as fp16x2 [n][jw]   (4 MB)
__device__ uint32_t g_UtH[(size_t)NCOLS * HW];     // U^T as fp16x2  [c][jw]   (32 MB)

// ---------------- helpers ----------------
__device__ __forceinline__ uint32_t s2u(const void* p) {
    uint32_t a;
    asm("{ .reg .u64 t; cvta.to.shared.u64 t, %1; cvt.u32.u64 %0, t; }" : "=r"(a) : "l"(p));
    return a;
}
__device__ __forceinline__ void cp16(uint32_t dst_smem, const uint32_t* src) {
    asm volatile("cp.async.cg.shared.global [%0], [%1], 16;"
                 :: "r"(dst_smem), "l"(__cvta_generic_to_global(src)));
}
__device__ __forceinline__ uint32_t pack2(float lo, float hi) {
    __half2 h = __floats2half2_rn(lo, hi);
    return *reinterpret_cast<uint32_t*>(&h);
}

// ---------------- pre-pass 1: pred f32 -> fp16x2 words ----------------
__global__ __launch_bounds__(256)
void pred_cvt_kernel(const float* __restrict__ pred)
{
    size_t i = ((size_t)blockIdx.x * 256 + threadIdx.x) * 4;   // 4 f32 -> 2 words
    const float4 v = *reinterpret_cast<const float4*>(pred + i);
    uint2 w;
    w.x = pack2(v.x, v.y);
    w.y = pack2(v.z, v.w);
    *reinterpret_cast<uint2*>(g_predH + i / 2) = w;
}

// ---------------- pre-pass 2: U[j][c] -> g_UtH[c][jw] (fp16x2) ----------------
__global__ __launch_bounds__(256)
void transpose_cvt_kernel(const float* __restrict__ U)
{
    __shared__ float t[32][33];
    const int c0 = blockIdx.x * 32;
    const int j0 = blockIdx.y * 32;
    const int tx = threadIdx.x & 31, ty = threadIdx.x >> 5;
    #pragma unroll
    for (int i = 0; i < 4; i++) {
        int j = ty + i * 8;
        t[j][tx] = U[(size_t)(j0 + j) * NCOLS + c0 + tx];
    }
    __syncthreads();
    // write 32 c-rows x 16 words
    #pragma unroll
    for (int it = 0; it < 2; it++) {
        int idx = threadIdx.x + it * 256;   // 0..511
        int cc = idx >> 4, jw = idx & 15;
        g_UtH[(size_t)(c0 + cc) * HW + (j0 >> 1) + jw] =
            pack2(t[2 * jw][cc], t[2 * jw + 1][cc]);
    }
}

// ---------------- main kernel: 128 threads (4 warps), 2 CTAs/SM ----------------
__global__ __launch_bounds__(128, 2)
void bilinear_main(const float* __restrict__ args,
                   const float* __restrict__ bias1,
                   const float* __restrict__ bias2,
                   float* __restrict__ out)
{
    extern __shared__ char smem[];
    const uint32_t sb = s2u(smem);
    const int tid  = threadIdx.x;
    const int lane = tid & 31, wid = tid >> 5;
    const int warp_m = wid & 1;     // 2 bands of 64 rows
    const int warp_n = wid >> 1;    // 2 bands of 64 cols
    const int gid = lane >> 2, tig = lane & 3;
    const int m_base = blockIdx.x * MT;
    const int r = blockIdx.y;

    const uint32_t* __restrict__ srcA = g_predH + (size_t)m_base * HW;
    const uint32_t* __restrict__ srcB = g_UtH + (size_t)r * HID * HW;

    // per-thread staging coords: 128 rows x 8 chunks of 16B; 128 threads x 8 iters
    const int sRow = tid >> 3;
    const int sQc  = tid & 7;
    const uint32_t sOff = (uint32_t)sRow * 128 + (((uint32_t)sQc * 16) ^ (((uint32_t)sRow & 7) << 4));
    const size_t  sSrc = (size_t)sRow * HW + sQc * 4;

    // ldmatrix per-lane address components
    const int aRowL = (lane & 7) + ((lane >> 3) & 1) * 8;   // row within 16-row A block
    const int aKwL  = (lane >> 4) * 4;                      // 0 or 4 word offset
    const int bRowL = (lane & 7) + ((lane >> 4) & 1) * 8;   // row within 16-row B block
    const int bKwL  = ((lane >> 3) & 1) * 4;

    float outp[8];
    #pragma unroll
    for (int t = 0; t < 8; t++) outp[t] = 0.f;

    float acc[4][8][4];
    #pragma unroll
    for (int a = 0; a < 4; a++)
        #pragma unroll
        for (int b = 0; b < 8; b++)
            #pragma unroll
            for (int c = 0; c < 4; c++) acc[a][b][c] = 0.f;

    // flat stage s -> (nc = s>>3, kt = s&7); buffer = s%3
    auto issue_stage = [&](int s, int buf) {
        const int kt = s & (KITER - 1);
        const int nc = s >> 3;
        const uint32_t aS = sb + SM_A + buf * SA_BYTES;
        const uint32_t bS = sb + SM_B + buf * SB_BYTES;
        const uint32_t* a0 = srcA + kt * (KT / 2) + sSrc;
        const uint32_t* b0 = srcB + (size_t)(nc * NT) * HW + kt * (KT / 2) + sSrc;
        #pragma unroll
        for (int it = 0; it < 8; it++)
            cp16(aS + sOff + it * 16 * 128, a0 + (size_t)it * 16 * HW);
        #pragma unroll
        for (int it = 0; it < 8; it++)
            cp16(bS + sOff + it * 16 * 128, b0 + (size_t)it * 16 * HW);
    };

    issue_stage(0, 0);
    asm volatile("cp.async.commit_group;" ::: "memory");
    issue_stage(1, 1);
    asm volatile("cp.async.commit_group;" ::: "memory");

    int buf = 0, buf2 = 2;
    for (int s = 0; s < NSTAGE_TOT; s++) {
        asm volatile("cp.async.wait_group 1;" ::: "memory");
        __syncthreads();
        if (s + 2 < NSTAGE_TOT) issue_stage(s + 2, buf2);
        asm volatile("cp.async.commit_group;" ::: "memory");

        const uint32_t aBase = sb + SM_A + buf * SA_BYTES;
        const uint32_t bBase = sb + SM_B + buf * SB_BYTES;

        #pragma unroll
        for (int ks = 0; ks < 4; ks++) {     // 4 x k16 per 64-K stage
            uint32_t af[4][4];
            #pragma unroll
            for (int wm = 0; wm < 4; wm++) {
                int row = warp_m * 64 + wm * 16 + aRowL;
                int kw  = ks * 8 + aKwL;
                uint32_t addr = aBase + row * 128 + 4 * (kw ^ ((row & 7) << 2));
                asm volatile("ldmatrix.sync.aligned.m8n8.x4.shared.b16 {%0,%1,%2,%3}, [%4];"
                             : "=r"(af[wm][0]), "=r"(af[wm][1]),
                               "=r"(af[wm][2]), "=r"(af[wm][3]) : "r"(addr));
            }
            uint32_t bf[8][2];
            #pragma unroll
            for (int p = 0; p < 4; p++) {    // each x4 covers 2 n-octets
                int row = warp_n * 64 + p * 16 + bRowL;
                int kw  = ks * 8 + bKwL;
                uint32_t addr = bBase + row * 128 + 4 * (kw ^ ((row & 7) << 2));
                asm volatile("ldmatrix.sync.aligned.m8n8.x4.shared.b16 {%0,%1,%2,%3}, [%4];"
                             : "=r"(bf[2 * p][0]), "=r"(bf[2 * p][1]),
                               "=r"(bf[2 * p + 1][0]), "=r"(bf[2 * p + 1][1]) : "r"(addr));
            }
            #pragma unroll
            for (int wn = 0; wn < 8; wn++)
                #pragma unroll
                for (int wm = 0; wm < 4; wm++) {
                    asm volatile(
                        "mma.sync.aligned.m16n8k16.row.col.f32.f16.f16.f32 "
                        "{%0,%1,%2,%3}, {%4,%5,%6,%7}, {%8,%9}, {%0,%1,%2,%3};"
                        : "+f"(acc[wm][wn][0]), "+f"(acc[wm][wn][1]),
                          "+f"(acc[wm][wn][2]), "+f"(acc[wm][wn][3])
                        : "r"(af[wm][0]), "r"(af[wm][1]),
                          "r"(af[wm][2]), "r"(af[wm][3]),
                          "r"(bf[wn][0]), "r"(bf[wn][1]));
                }
        }

        // ---- chunk boundary: fused epilogue (overlaps in-flight cp.async) ----
        if ((s & (KITER - 1)) == (KITER - 1)) {
            const int nc = s >> 3;
            const float* b1p = bias1 + (size_t)r * HID + nc * NT;
            #pragma unroll
            for (int wm = 0; wm < 4; wm++)
                #pragma unroll
                for (int i = 0; i < 2; i++) {
                    int m_loc = warp_m * 64 + wm * 16 + gid + i * 8;
                    const float* arow = args + (size_t)(m_base + m_loc) * HID + nc * NT;
                    float sm = 0.f;
                    #pragma unroll
                    for (int wn = 0; wn < 8; wn++) {
                        int c = warp_n * 64 + wn * 8 + tig * 2;
                        const float2 av = *reinterpret_cast<const float2*>(arow + c);
                        const float2 bv = *reinterpret_cast<const float2*>(b1p + c);
                        sm += (acc[wm][wn][i * 2]     + bv.x) * av.x
                            + (acc[wm][wn][i * 2 + 1] + bv.y) * av.y;
                    }
                    outp[wm * 2 + i] += sm;
                }
            #pragma unroll
            for (int a = 0; a < 4; a++)
                #pragma unroll
                for (int b = 0; b < 8; b++)
                    #pragma unroll
                    for (int c = 0; c < 4; c++) acc[a][b][c] = 0.f;
        }

        buf  = (buf  == 2) ? 0 : buf  + 1;
        buf2 = (buf2 == 2) ? 0 : buf2 + 1;
    }

    // ---- reduce over tig lanes ----
    #pragma unroll
    for (int t = 0; t < 8; t++) {
        outp[t] += __shfl_xor_sync(0xffffffffu, outp[t], 1);
        outp[t] += __shfl_xor_sync(0xffffffffu, outp[t], 2);
    }

    // ---- cross warp_n reduce via shared, one store per output row ----
    float* sred = reinterpret_cast<float*>(smem + SM_RED);
    sred[tid] = 0.f;
    __syncthreads();
    if (tig == 0) {
        #pragma unroll
        for (int wm = 0; wm < 4; wm++)
            #pragma unroll
            for (int i = 0; i < 2; i++)
                atomicAdd(&sred[warp_m * 64 + wm * 16 + gid + i * 8], outp[wm * 2 + i]);
    }
    __syncthreads();
    out[(size_t)(m_base + tid) * ROLES + r] = sred[tid] + __ldg(&bias2[r]);
}

// ---------------- launch ----------------
extern "C" void kernel_launch(void* const* d_in, const int* in_sizes, int n_in,
                              void* d_out, int out_size) {
    const float* pred  = (const float*)d_in[0];
    const float* args  = (const float*)d_in[1];
    const float* U     = (const float*)d_in[2];
    const float* bias1 = (const float*)d_in[3];
    const float* bias2 = (const float*)d_in[4];
    float* out = (float*)d_out;

    cudaFuncSetAttribute(bilinear_main, cudaFuncAttributeMaxDynamicSharedMemorySize, SM_TOTAL);

    pred_cvt_kernel<<<(NTOK * HID) / (256 * 4), 256>>>(pred);
    transpose_cvt_kernel<<<dim3(NCOLS / 32, HID / 32), 256>>>(U);
    bilinear_main<<<dim3(NTOK / MT, ROLES), 128, SM_TOTAL>>>(args, bias1, bias2, out);
}